// round 2
// baseline (speedup 1.0000x reference)
#include <cuda_runtime.h>
#include <math.h>

// Problem constants
#define Bq 2
#define Sq 2048
#define Dq 512
#define Hq 8

// ---------------- scratch (device globals; no allocation allowed) ----------
__device__ float g_q[(size_t)Bq * Hq * Sq * Dq];      // 64 MB  [b,h,s,e]
__device__ float g_k[(size_t)Bq * Hq * Sq * Dq];      // 64 MB
__device__ float g_v[(size_t)Bq * Hq * Sq * Dq];      // 64 MB
__device__ float g_attn[(size_t)Bq * Hq * Sq * Sq];   // 256 MB [b,h,s,k]
__device__ float g_z[(size_t)Bq * Sq * Hq * Dq];      // 64 MB  [b,s,h,e] (concat layout)

// Batch-offset descriptor: offset(z) = (z / dv) * s1 + (z % md) * s2
struct Off {
    int dv; long s1; int md; long s2;
};

// ---------------------------------------------------------------------------
// Generic tiled SGEMM: C = alpha * A @ op(B) (+ bias), all row-major fp32.
// BT=false: op(B)=B [K,N].  BT=true: op(B)=B^T with B stored [N,K].
// Tile 128x128xBK8, 256 threads, 8x8 per thread. All dims multiples of 128/8.
// ---------------------------------------------------------------------------
template <bool BT>
__global__ void __launch_bounds__(256)
sgemm_kernel(const float* __restrict__ A, const float* __restrict__ Bm,
             float* __restrict__ C,
             int M, int N, int K, int lda, int ldb, int ldc,
             Off oa, Off ob, Off oc,
             float alpha, const float* __restrict__ bias)
{
    const int z = blockIdx.z;
    A  += (long)(z / oa.dv) * oa.s1 + (long)(z % oa.md) * oa.s2;
    Bm += (long)(z / ob.dv) * ob.s1 + (long)(z % ob.md) * ob.s2;
    C  += (long)(z / oc.dv) * oc.s1 + (long)(z % oc.md) * oc.s2;

    __shared__ float As[8][128];
    __shared__ float Bs[8][128];

    const int tid = threadIdx.x;
    const int tx = tid & 15;     // 0..15 -> N direction
    const int ty = tid >> 4;     // 0..15 -> M direction
    const int row0 = blockIdx.y * 128;
    const int col0 = blockIdx.x * 128;

    // global->shared load indices
    const int grow = tid >> 1;          // 0..127
    const int gcol = (tid & 1) * 4;     // 0 or 4
    const int brow = tid >> 5;          // 0..7   (NN)
    const int bcol = (tid & 31) * 4;    // 0..124 (NN)

    float acc[8][8];
    #pragma unroll
    for (int i = 0; i < 8; ++i)
        #pragma unroll
        for (int j = 0; j < 8; ++j) acc[i][j] = 0.0f;

    for (int k0 = 0; k0 < K; k0 += 8) {
        // A tile: [128 rows x 8 k]  (A row-major, contiguous in k)
        float4 av = *(const float4*)&A[(long)(row0 + grow) * lda + (k0 + gcol)];
        As[gcol + 0][grow] = av.x;
        As[gcol + 1][grow] = av.y;
        As[gcol + 2][grow] = av.z;
        As[gcol + 3][grow] = av.w;

        if (BT) {
            // B stored [N,K]: Bs[k][n] = B[n, k]
            float4 bv = *(const float4*)&Bm[(long)(col0 + grow) * ldb + (k0 + gcol)];
            Bs[gcol + 0][grow] = bv.x;
            Bs[gcol + 1][grow] = bv.y;
            Bs[gcol + 2][grow] = bv.z;
            Bs[gcol + 3][grow] = bv.w;
        } else {
            // B stored [K,N]: direct vectorized row copy
            *(float4*)&Bs[brow][bcol] =
                *(const float4*)&Bm[(long)(k0 + brow) * ldb + (col0 + bcol)];
        }
        __syncthreads();

        #pragma unroll
        for (int k = 0; k < 8; ++k) {
            float a[8], b[8];
            #pragma unroll
            for (int i = 0; i < 8; ++i) a[i] = As[k][ty * 8 + i];
            #pragma unroll
            for (int j = 0; j < 8; ++j) b[j] = Bs[k][tx * 8 + j];
            #pragma unroll
            for (int i = 0; i < 8; ++i)
                #pragma unroll
                for (int j = 0; j < 8; ++j)
                    acc[i][j] = fmaf(a[i], b[j], acc[i][j]);
        }
        __syncthreads();
    }

    #pragma unroll
    for (int i = 0; i < 8; ++i) {
        const long r = row0 + ty * 8 + i;
        #pragma unroll
        for (int j = 0; j < 8; j += 4) {
            const int c = col0 + tx * 8 + j;
            float4 v;
            v.x = acc[i][j + 0] * alpha;
            v.y = acc[i][j + 1] * alpha;
            v.z = acc[i][j + 2] * alpha;
            v.w = acc[i][j + 3] * alpha;
            if (bias) {
                v.x += bias[c + 0];
                v.y += bias[c + 1];
                v.z += bias[c + 2];
                v.w += bias[c + 3];
            }
            *(float4*)&C[r * ldc + c] = v;
        }
    }
}

// ---------------------------------------------------------------------------
// Row softmax over g_attn rows of length Sq. One block (256 thr) per row.
// ---------------------------------------------------------------------------
__global__ void __launch_bounds__(256) softmax_kernel()
{
    const long row = blockIdx.x;            // 0 .. B*H*S-1
    float* p = g_attn + row * (long)Sq;
    const int tid = threadIdx.x;

    float v[8];
    float mx = -1e30f;
    #pragma unroll
    for (int i = 0; i < 8; ++i) {
        v[i] = p[tid + i * 256];
        mx = fmaxf(mx, v[i]);
    }
    #pragma unroll
    for (int o = 16; o > 0; o >>= 1) mx = fmaxf(mx, __shfl_xor_sync(0xFFFFFFFFu, mx, o));

    __shared__ float sred[8];
    if ((tid & 31) == 0) sred[tid >> 5] = mx;
    __syncthreads();
    float m = sred[0];
    #pragma unroll
    for (int i = 1; i < 8; ++i) m = fmaxf(m, sred[i]);
    __syncthreads();

    float s = 0.0f;
    #pragma unroll
    for (int i = 0; i < 8; ++i) {
        v[i] = __expf(v[i] - m);
        s += v[i];
    }
    #pragma unroll
    for (int o = 16; o > 0; o >>= 1) s += __shfl_xor_sync(0xFFFFFFFFu, s, o);
    if ((tid & 31) == 0) sred[tid >> 5] = s;
    __syncthreads();
    float tot = 0.0f;
    #pragma unroll
    for (int i = 0; i < 8; ++i) tot += sred[i];

    const float inv = 1.0f / tot;
    #pragma unroll
    for (int i = 0; i < 8; ++i) p[tid + i * 256] = v[i] * inv;
}

// ---------------------------------------------------------------------------
// attn_avg[b,s,k] = mean_h attn[b,h,s,k]   (float4 per thread)
// ---------------------------------------------------------------------------
__global__ void __launch_bounds__(256) avg_kernel(float* __restrict__ out)
{
    const long idx = (long)blockIdx.x * 256 + threadIdx.x;   // float4 index
    const long per_b = (long)Sq * Sq / 4;
    const long b = idx / per_b;
    const long r = idx % per_b;

    const float4* base = (const float4*)g_attn;
    float4 acc = make_float4(0.f, 0.f, 0.f, 0.f);
    #pragma unroll
    for (int h = 0; h < Hq; ++h) {
        float4 t = base[(b * Hq + h) * per_b + r];
        acc.x += t.x; acc.y += t.y; acc.z += t.z; acc.w += t.w;
    }
    const float inv = 1.0f / Hq;
    acc.x *= inv; acc.y *= inv; acc.z *= inv; acc.w *= inv;
    ((float4*)out)[b * per_b + r] = acc;
}

// ---------------------------------------------------------------------------
extern "C" void kernel_launch(void* const* d_in, const int* in_sizes, int n_in,
                              void* d_out, int out_size)
{
    (void)in_sizes; (void)n_in; (void)out_size;

    const float* Xq = (const float*)d_in[0];
    const float* Xk = (const float*)d_in[1];
    const float* Xv = (const float*)d_in[2];
    const float* Wq = (const float*)d_in[3];
    const float* Wk = (const float*)d_in[4];
    const float* Wv = (const float*)d_in[5];
    const float* Wz = (const float*)d_in[6];
    const float* bz = (const float*)d_in[7];
    float* out = (float*)d_out;                          // [B,S,D]
    float* attn_avg = out + (long)Bq * Sq * Dq;          // [B,S,S]

    float *pq, *pk, *pv, *pattn, *pz;
    cudaGetSymbolAddress((void**)&pq, g_q);
    cudaGetSymbolAddress((void**)&pk, g_k);
    cudaGetSymbolAddress((void**)&pv, g_v);
    cudaGetSymbolAddress((void**)&pattn, g_attn);
    cudaGetSymbolAddress((void**)&pz, g_z);

    const long SD = (long)Sq * Dq;
    const long SS = (long)Sq * Sq;
    const long DD = (long)Dq * Dq;

    // --- QKV projections: per (b,h): [S,D] = X[b] @ W[h], 16 batches --------
    {
        dim3 grid(Dq / 128, Sq / 128, Bq * Hq);
        Off oa = { Hq, SD, 1, 0 };          // A = X[b]
        Off oc = { 1,  SD, 1, 0 };          // C = buf[z]
        Off obq = { 1, 0, Hq, DD };         // B = W[h]
        sgemm_kernel<false><<<grid, 256>>>(Xq, Wq, pq, Sq, Dq, Dq, Dq, Dq, Dq,
                                           oa, obq, oc, 1.0f, nullptr);
        sgemm_kernel<false><<<grid, 256>>>(Xk, Wk, pk, Sq, Dq, Dq, Dq, Dq, Dq,
                                           oa, obq, oc, 1.0f, nullptr);
        sgemm_kernel<false><<<grid, 256>>>(Xv, Wv, pv, Sq, Dq, Dq, Dq, Dq, Dq,
                                           oa, obq, oc, 1.0f, nullptr);
    }

    // --- scores: attn[z] = (1/sqrt(D)) * Q[z] @ K[z]^T -----------------------
    {
        dim3 grid(Sq / 128, Sq / 128, Bq * Hq);
        Off oa = { 1, SD, 1, 0 };
        Off ob = { 1, SD, 1, 0 };
        Off oc = { 1, SS, 1, 0 };
        const float scale = (float)(1.0 / sqrt((double)Dq));
        sgemm_kernel<true><<<grid, 256>>>(pq, pk, pattn, Sq, Sq, Dq, Dq, Dq, Sq,
                                          oa, ob, oc, scale, nullptr);
    }

    // --- softmax (in place) ---------------------------------------------------
    softmax_kernel<<<Bq * Hq * Sq, 256>>>();

    // --- head-average into output ----------------------------------------------
    avg_kernel<<<(Bq * SS / 4) / 256, 256>>>(attn_avg);

    // --- z[z] = attn[z] @ V[z], written in concat layout [b,s,h*D+e] ----------
    {
        dim3 grid(Dq / 128, Sq / 128, Bq * Hq);
        Off oa = { 1, SS, 1, 0 };
        Off ob = { 1, SD, 1, 0 };
        Off oc = { Hq, (long)Sq * Hq * Dq, Hq, Dq };
        sgemm_kernel<false><<<grid, 256>>>(pattn, pv, pz, Sq, Dq, Sq, Sq, Dq, Hq * Dq,
                                           oa, ob, oc, 1.0f, nullptr);
    }

    // --- out = zcat @ Wz + bz ---------------------------------------------------
    {
        dim3 grid(Dq / 128, (Bq * Sq) / 128, 1);
        Off oa = { 1, 0, 1, 0 };
        Off ob = { 1, 0, 1, 0 };
        Off oc = { 1, 0, 1, 0 };
        sgemm_kernel<false><<<grid, 256>>>(pz, Wz, out, Bq * Sq, Dq, Hq * Dq,
                                           Hq * Dq, Dq, Dq,
                                           oa, ob, oc, 1.0f, bz);
    }
}

// round 4
// speedup vs baseline: 1.8190x; 1.8190x over previous
#include <cuda_runtime.h>
#include <cuda_bf16.h>
#include <math.h>
#include <stdint.h>

#define Bq 2
#define Sq 2048
#define Dq 512
#define Hq 8

#define SDc  ((long)Sq * Dq)
#define SSc  ((long)Sq * Sq)
#define DDc  ((long)Dq * Dq)

#define X_PLANE    ((long)Bq * Sq * Dq)
#define W_PLANE    ((long)Hq * Dq * Dq)
#define QK_PLANE   ((long)Bq * Hq * Sq * Dq)
#define ATTN_PLANE ((long)Bq * Hq * Sq * Sq)
#define Z_PLANE    QK_PLANE

__device__ __align__(256) float g_attn[ATTN_PLANE];
__device__ __align__(256) __nv_bfloat16 g_xq [2 * X_PLANE];
__device__ __align__(256) __nv_bfloat16 g_xk [2 * X_PLANE];
__device__ __align__(256) __nv_bfloat16 g_xv [2 * X_PLANE];
__device__ __align__(256) __nv_bfloat16 g_wqt[2 * W_PLANE];
__device__ __align__(256) __nv_bfloat16 g_wkt[2 * W_PLANE];
__device__ __align__(256) __nv_bfloat16 g_wvt[2 * W_PLANE];
__device__ __align__(256) __nv_bfloat16 g_wzt[2 * W_PLANE];
__device__ __align__(256) __nv_bfloat16 g_qs [2 * QK_PLANE];
__device__ __align__(256) __nv_bfloat16 g_ks [2 * QK_PLANE];
__device__ __align__(256) __nv_bfloat16 g_vts[2 * QK_PLANE];   // [b,h,e,s]
__device__ __align__(256) __nv_bfloat16 g_zs [2 * Z_PLANE];    // [b,s,h*D]
__device__ __align__(256) __nv_bfloat16 g_ps [2 * ATTN_PLANE]; // split probs

struct Off { int dv; long s1; int md; long s2; };

__device__ __forceinline__ uint32_t smem_u32(const void* p) {
    uint32_t a;
    asm("{ .reg .u64 t; cvta.to.shared.u64 t, %1; cvt.u32.u64 %0, t; }" : "=r"(a) : "l"(p));
    return a;
}
__device__ __forceinline__ void cpasync16(uint32_t dst, const void* src) {
    asm volatile("cp.async.cg.shared.global [%0], [%1], 16;" :: "r"(dst), "l"(src) : "memory");
}
#define CP_COMMIT() asm volatile("cp.async.commit_group;" ::: "memory")
#define CP_WAIT1()  asm volatile("cp.async.wait_group 1;" ::: "memory")
#define CP_WAIT0()  asm volatile("cp.async.wait_group 0;" ::: "memory")

#define LDSM4(r, a) \
    asm volatile("ldmatrix.sync.aligned.m8n8.x4.shared.b16 {%0,%1,%2,%3}, [%4];" \
        : "=r"((r)[0]), "=r"((r)[1]), "=r"((r)[2]), "=r"((r)[3]) : "r"(a))

#define MMA(c, a, b0, b1) \
    asm volatile("mma.sync.aligned.m16n8k16.row.col.f32.bf16.bf16.f32 " \
        "{%0,%1,%2,%3},{%4,%5,%6,%7},{%8,%9},{%0,%1,%2,%3};" \
        : "+f"((c)[0]), "+f"((c)[1]), "+f"((c)[2]), "+f"((c)[3]) \
        : "r"((a)[0]), "r"((a)[1]), "r"((a)[2]), "r"((a)[3]), "r"(b0), "r"(b1))

__device__ __forceinline__ void split1(float x, __nv_bfloat16& h, __nv_bfloat16& l) {
    h = __float2bfloat16_rn(x);
    l = __float2bfloat16_rn(x - __bfloat162float(h));
}

#define STAGE_B  16384
#define STAGE_SZ 32768
#define SMEM_SZ  (2 * STAGE_SZ)

// ---------------------------------------------------------------------------
// HMMA TN GEMM, 3-pass bf16 split. Block 128x128, K-chunk 32, 8 warps.
// Smem row layout: 128B per row = [32 bf16 hi | 32 bf16 lo], chunk XOR swizzle.
// mode 0: fp32 out (+bias). mode 1: split-bf16 out. mode 2: split-bf16 transposed.
// ---------------------------------------------------------------------------
__global__ void __launch_bounds__(256, 1)
gemm_mma(const __nv_bfloat16* __restrict__ A, long aplane,
         const __nv_bfloat16* __restrict__ B, long bplane,
         void* Cv, long cplane,
         int K, int lda, int ldb, int ldc,
         Off oa, Off ob, Off oc,
         float alpha, const float* __restrict__ bias, int mode)
{
    extern __shared__ char smem[];
    const uint32_t sm = smem_u32(smem);
    const int tid = threadIdx.x, wid = tid >> 5, lane = tid & 31;
    const int z = blockIdx.z;

    const __nv_bfloat16* Ah = A + (long)(z / oa.dv) * oa.s1 + (long)(z % oa.md) * oa.s2;
    const __nv_bfloat16* Bh = B + (long)(z / ob.dv) * ob.s1 + (long)(z % ob.md) * ob.s2;
    const long coff = (long)(z / oc.dv) * oc.s1 + (long)(z % oc.md) * oc.s2;

    const long row0 = (long)blockIdx.y * 128;
    const long col0 = (long)blockIdx.x * 128;

    // ---- loader thread mapping: 2 threads per row (hi / lo plane, 64B each)
    const int lrow = tid >> 1;
    const int lpl  = tid & 1;
    const __nv_bfloat16* Asrc = (lpl ? Ah + aplane : Ah) + (row0 + lrow) * lda;
    const __nv_bfloat16* Bsrc = (lpl ? Bh + bplane : Bh) + (col0 + lrow) * ldb;
    uint32_t soff[4];
    #pragma unroll
    for (int j = 0; j < 4; ++j) {
        const int c = lpl * 4 + j;
        soff[j] = lrow * 128 + ((c ^ (lrow & 7)) << 4);
    }

    // ---- compute thread mapping
    const int wm = wid & 1, wn = wid >> 1;
    const int g = lane >> 3, r8 = lane & 7;
    const int a_roff = ((g & 1) << 3) + r8;   // row within m16 tile
    const int a_kh   = g >> 1;                // k-half
    const int b_roff = ((g >> 1) << 3) + r8;  // row within n16 pair
    const int b_kh   = g & 1;

    float acc[4][4][4];
    #pragma unroll
    for (int i = 0; i < 4; ++i)
        #pragma unroll
        for (int j = 0; j < 4; ++j)
            #pragma unroll
            for (int q = 0; q < 4; ++q) acc[i][j][q] = 0.0f;

    const int nst = K / 32;

    // prologue: stage 0
    {
        const uint32_t tb = sm;
        #pragma unroll
        for (int j = 0; j < 4; ++j) {
            cpasync16(tb + soff[j], Asrc + j * 8);
            cpasync16(tb + STAGE_B + soff[j], Bsrc + j * 8);
        }
        CP_COMMIT();
    }

    for (int s = 0; s < nst; ++s) {
        if (s + 1 < nst) {
            const uint32_t tb = sm + ((s + 1) & 1) * STAGE_SZ;
            const long k0 = (long)(s + 1) * 32;
            #pragma unroll
            for (int j = 0; j < 4; ++j) {
                cpasync16(tb + soff[j], Asrc + k0 + j * 8);
                cpasync16(tb + STAGE_B + soff[j], Bsrc + k0 + j * 8);
            }
            CP_COMMIT();
            CP_WAIT1();
        } else {
            CP_WAIT0();
        }
        __syncthreads();

        const uint32_t tb = sm + (s & 1) * STAGE_SZ;
        #pragma unroll
        for (int ks = 0; ks < 2; ++ks) {
            uint32_t Ahr[4][4], Alr[4][4], Bhr[2][4], Blr[2][4];
            #pragma unroll
            for (int mt = 0; mt < 4; ++mt) {
                const int row = wm * 64 + mt * 16 + a_roff;
                const uint32_t base = tb + row * 128;
                const int c0 = ks * 2 + a_kh;
                LDSM4(Ahr[mt], base + ((c0 ^ (row & 7)) << 4));
                LDSM4(Alr[mt], base + (((c0 + 4) ^ (row & 7)) << 4));
            }
            #pragma unroll
            for (int np = 0; np < 2; ++np) {
                const int row = wn * 32 + np * 16 + b_roff;
                const uint32_t base = tb + STAGE_B + row * 128;
                const int c0 = ks * 2 + b_kh;
                LDSM4(Bhr[np], base + ((c0 ^ (row & 7)) << 4));
                LDSM4(Blr[np], base + (((c0 + 4) ^ (row & 7)) << 4));
            }
            #pragma unroll
            for (int mt = 0; mt < 4; ++mt)
                #pragma unroll
                for (int nt = 0; nt < 4; ++nt) {
                    const int np = nt >> 1, s2 = (nt & 1) * 2;
                    MMA(acc[mt][nt], Ahr[mt], Bhr[np][s2], Bhr[np][s2 + 1]);
                    MMA(acc[mt][nt], Ahr[mt], Blr[np][s2], Blr[np][s2 + 1]);
                    MMA(acc[mt][nt], Alr[mt], Bhr[np][s2], Bhr[np][s2 + 1]);
                }
        }
        __syncthreads();
    }

    // ---- epilogue
    const int r_in = lane >> 2, c_in = (lane & 3) * 2;
    #pragma unroll
    for (int mt = 0; mt < 4; ++mt) {
        #pragma unroll
        for (int half = 0; half < 2; ++half) {
            const long row = row0 + wm * 64 + mt * 16 + half * 8 + r_in;
            #pragma unroll
            for (int nt = 0; nt < 4; ++nt) {
                const int colg = (int)col0 + wn * 32 + nt * 8 + c_in;
                float v0 = acc[mt][nt][half * 2 + 0] * alpha;
                float v1 = acc[mt][nt][half * 2 + 1] * alpha;
                if (mode == 0) {
                    if (bias) { v0 += bias[colg]; v1 += bias[colg + 1]; }
                    *(float2*)((float*)Cv + coff + row * ldc + colg) = make_float2(v0, v1);
                } else if (mode == 1) {
                    __nv_bfloat16 h0, l0, h1, l1;
                    split1(v0, h0, l0); split1(v1, h1, l1);
                    __nv_bfloat162 hh; hh.x = h0; hh.y = h1;
                    __nv_bfloat162 ll; ll.x = l0; ll.y = l1;
                    __nv_bfloat16* Ch = (__nv_bfloat16*)Cv + coff + row * ldc + colg;
                    *(__nv_bfloat162*)Ch = hh;
                    *(__nv_bfloat162*)(Ch + cplane) = ll;
                } else {
                    __nv_bfloat16 h0, l0, h1, l1;
                    split1(v0, h0, l0); split1(v1, h1, l1);
                    __nv_bfloat16* Ch = (__nv_bfloat16*)Cv + coff;
                    const long o0 = (long)colg * ldc + row;
                    const long o1 = (long)(colg + 1) * ldc + row;
                    Ch[o0] = h0; Ch[o0 + cplane] = l0;
                    Ch[o1] = h1; Ch[o1 + cplane] = l1;
                }
            }
        }
    }
}

// ---------------------------------------------------------------------------
__global__ void __launch_bounds__(256) split_kernel(const float* __restrict__ in,
                                                    __nv_bfloat16* __restrict__ hi, long plane)
{
    const long idx = (long)blockIdx.x * 256 + threadIdx.x;
    float4 v = ((const float4*)in)[idx];
    __nv_bfloat16 h0, l0, h1, l1, h2, l2, h3, l3;
    split1(v.x, h0, l0); split1(v.y, h1, l1);
    split1(v.z, h2, l2); split1(v.w, h3, l3);
    __nv_bfloat162 a, b, c, d;
    a.x = h0; a.y = h1; b.x = h2; b.y = h3;
    c.x = l0; c.y = l1; d.x = l2; d.y = l3;
    ((__nv_bfloat162*)hi)[2 * idx]     = a;
    ((__nv_bfloat162*)hi)[2 * idx + 1] = b;
    ((__nv_bfloat162*)(hi + plane))[2 * idx]     = c;
    ((__nv_bfloat162*)(hi + plane))[2 * idx + 1] = d;
}

// transpose + split: in [z][R][C] fp32 -> out [z][C][R] bf16 hi/lo
__global__ void __launch_bounds__(256) tsplit_kernel(const float* __restrict__ in,
                                                     __nv_bfloat16* __restrict__ outh,
                                                     long plane, int R, int C)
{
    __shared__ float ts[32][33];
    const int tx = threadIdx.x, ty = threadIdx.y;
    const long zo = (long)blockIdx.z * R * C;
    const int r0 = blockIdx.y * 32, c0 = blockIdx.x * 32;
    #pragma unroll
    for (int i = 0; i < 4; ++i)
        ts[ty + 8 * i][tx] = in[zo + (long)(r0 + ty + 8 * i) * C + c0 + tx];
    __syncthreads();
    #pragma unroll
    for (int i = 0; i < 4; ++i) {
        __nv_bfloat16 h, l;
        split1(ts[tx][ty + 8 * i], h, l);
        const long o = zo + (long)(c0 + ty + 8 * i) * R + r0 + tx;
        outh[o] = h;
        outh[o + plane] = l;
    }
}

// softmax over fp32 rows of g_attn -> split bf16 probs in g_ps
__global__ void __launch_bounds__(256) softmax_kernel()
{
    const long rowo = (long)blockIdx.x * Sq;
    const float* p = g_attn + rowo;
    const int tid = threadIdx.x;

    float v[8];
    float mx = -1e30f;
    #pragma unroll
    for (int i = 0; i < 8; ++i) { v[i] = p[tid + i * 256]; mx = fmaxf(mx, v[i]); }
    #pragma unroll
    for (int o = 16; o > 0; o >>= 1) mx = fmaxf(mx, __shfl_xor_sync(~0u, mx, o));
    __shared__ float sr[8];
    if ((tid & 31) == 0) sr[tid >> 5] = mx;
    __syncthreads();
    float m = sr[0];
    #pragma unroll
    for (int i = 1; i < 8; ++i) m = fmaxf(m, sr[i]);
    __syncthreads();
    float s = 0.f;
    #pragma unroll
    for (int i = 0; i < 8; ++i) { v[i] = __expf(v[i] - m); s += v[i]; }
    #pragma unroll
    for (int o = 16; o > 0; o >>= 1) s += __shfl_xor_sync(~0u, s, o);
    if ((tid & 31) == 0) sr[tid >> 5] = s;
    __syncthreads();
    float t = 0.f;
    #pragma unroll
    for (int i = 0; i < 8; ++i) t += sr[i];
    const float inv = 1.0f / t;
    #pragma unroll
    for (int i = 0; i < 8; ++i) {
        __nv_bfloat16 h, l;
        split1(v[i] * inv, h, l);
        g_ps[rowo + tid + i * 256] = h;
        g_ps[ATTN_PLANE + rowo + tid + i * 256] = l;
    }
}

// attn_avg from split probs
__global__ void __launch_bounds__(256) avg_kernel(float* __restrict__ out)
{
    const long p2 = (long)blockIdx.x * 256 + threadIdx.x;
    const long per_b = SSc / 2;
    const long b = p2 / per_b, r = p2 % per_b;
    const __nv_bfloat162* hi = (const __nv_bfloat162*)g_ps;
    const __nv_bfloat162* lo = (const __nv_bfloat162*)(g_ps + ATTN_PLANE);
    float2 acc = make_float2(0.f, 0.f);
    #pragma unroll
    for (int h = 0; h < Hq; ++h) {
        const long o = (b * Hq + h) * per_b + r;
        __nv_bfloat162 a = hi[o], c = lo[o];
        acc.x += __bfloat162float(a.x) + __bfloat162float(c.x);
        acc.y += __bfloat162float(a.y) + __bfloat162float(c.y);
    }
    acc.x *= 0.125f; acc.y *= 0.125f;
    ((float2*)out)[p2] = acc;
}

// ---------------------------------------------------------------------------
extern "C" void kernel_launch(void* const* d_in, const int* in_sizes, int n_in,
                              void* d_out, int out_size)
{
    (void)in_sizes; (void)n_in; (void)out_size;
    const float* Xq = (const float*)d_in[0];
    const float* Xk = (const float*)d_in[1];
    const float* Xv = (const float*)d_in[2];
    const float* Wq = (const float*)d_in[3];
    const float* Wk = (const float*)d_in[4];
    const float* Wv = (const float*)d_in[5];
    const float* Wz = (const float*)d_in[6];
    const float* bz = (const float*)d_in[7];
    float* out = (float*)d_out;
    float* attn_avg = out + (long)Bq * Sq * Dq;

    __nv_bfloat16 *pxq, *pxk, *pxv, *pwq, *pwk, *pwv, *pwz, *pqs, *pks, *pvt, *pzs, *pps;
    float* pattn;
    cudaGetSymbolAddress((void**)&pxq, g_xq);
    cudaGetSymbolAddress((void**)&pxk, g_xk);
    cudaGetSymbolAddress((void**)&pxv, g_xv);
    cudaGetSymbolAddress((void**)&pwq, g_wqt);
    cudaGetSymbolAddress((void**)&pwk, g_wkt);
    cudaGetSymbolAddress((void**)&pwv, g_wvt);
    cudaGetSymbolAddress((void**)&pwz, g_wzt);
    cudaGetSymbolAddress((void**)&pqs, g_qs);
    cudaGetSymbolAddress((void**)&pks, g_ks);
    cudaGetSymbolAddress((void**)&pvt, g_vts);
    cudaGetSymbolAddress((void**)&pzs, g_zs);
    cudaGetSymbolAddress((void**)&pps, g_ps);
    cudaGetSymbolAddress((void**)&pattn, g_attn);

    cudaFuncSetAttribute(gemm_mma, cudaFuncAttributeMaxDynamicSharedMemorySize, SMEM_SZ);

    const float inv4 = (float)(1.0 / pow((double)Dq, 0.25));

    // 1) split inputs; transpose+split weights
    {
        int nb = (int)(X_PLANE / 1024);
        split_kernel<<<nb, 256>>>(Xq, pxq, X_PLANE);
        split_kernel<<<nb, 256>>>(Xk, pxk, X_PLANE);
        split_kernel<<<nb, 256>>>(Xv, pxv, X_PLANE);
        dim3 tb(32, 8);
        tsplit_kernel<<<dim3(16, 16, 8), tb>>>(Wq, pwq, W_PLANE, Dq, Dq);
        tsplit_kernel<<<dim3(16, 16, 8), tb>>>(Wk, pwk, W_PLANE, Dq, Dq);
        tsplit_kernel<<<dim3(16, 16, 8), tb>>>(Wv, pwv, W_PLANE, Dq, Dq);
        tsplit_kernel<<<dim3(16, 128, 1), tb>>>(Wz, pwz, W_PLANE, Hq * Dq, Dq);
    }

    // 2) projections: [S,512] = X[b] @ Wt[h]^T (TN), z = b*H+h
    {
        dim3 grid(Dq / 128, Sq / 128, Bq * Hq);
        Off oa = { Hq, SDc, 1, 0 };
        Off ob = { 1, 0, Hq, DDc };
        Off oc = { 1, SDc, 1, 0 };
        gemm_mma<<<grid, 256, SMEM_SZ>>>(pxq, X_PLANE, pwq, W_PLANE, pqs, QK_PLANE,
                                         Dq, Dq, Dq, Dq, oa, ob, oc, inv4, nullptr, 1);
        gemm_mma<<<grid, 256, SMEM_SZ>>>(pxk, X_PLANE, pwk, W_PLANE, pks, QK_PLANE,
                                         Dq, Dq, Dq, Dq, oa, ob, oc, inv4, nullptr, 1);
        gemm_mma<<<grid, 256, SMEM_SZ>>>(pxv, X_PLANE, pwv, W_PLANE, pvt, QK_PLANE,
                                         Dq, Dq, Dq, Sq, oa, ob, oc, 1.0f, nullptr, 2);
    }

    // 3) scores (fp32) = Q @ K^T
    {
        dim3 grid(Sq / 128, Sq / 128, Bq * Hq);
        Off oa = { 1, SDc, 1, 0 };
        Off ob = { 1, SDc, 1, 0 };
        Off oc = { 1, SSc, 1, 0 };
        gemm_mma<<<grid, 256, SMEM_SZ>>>(pqs, QK_PLANE, pks, QK_PLANE, pattn, 0,
                                         Dq, Dq, Dq, Sq, oa, ob, oc, 1.0f, nullptr, 0);
    }

    // 4) softmax -> split probs; 5) head average
    softmax_kernel<<<Bq * Hq * Sq, 256>>>();
    avg_kernel<<<(int)(Bq * SSc / 2 / 256), 256>>>(attn_avg);

    // 6) z = P @ V (B = V^T, TN), concat-layout split output
    {
        dim3 grid(Dq / 128, Sq / 128, Bq * Hq);
        Off oa = { 1, SSc, 1, 0 };
        Off ob = { 1, SDc, 1, 0 };
        Off oc = { Hq, (long)Sq * Hq * Dq, Hq, (long)Dq };
        gemm_mma<<<grid, 256, SMEM_SZ>>>(pps, ATTN_PLANE, pvt, QK_PLANE, pzs, Z_PLANE,
                                         Sq, Sq, Sq, Hq * Dq, oa, ob, oc, 1.0f, nullptr, 1);
    }

    // 7) out = Z @ Wz^T + bz (fp32)
    {
        dim3 grid(Dq / 128, (Bq * Sq) / 128, 1);
        Off oz = { 1, 0, 1, 0 };
        gemm_mma<<<grid, 256, SMEM_SZ>>>(pzs, Z_PLANE, pwz, W_PLANE, out, 0,
                                         Hq * Dq, Hq * Dq, Hq * Dq, Dq,
                                         oz, oz, oz, 1.0f, bz, 0);
    }
}

// round 6
// speedup vs baseline: 2.1685x; 1.1922x over previous
#include <cuda_runtime.h>
#include <cuda_bf16.h>
#include <math.h>
#include <stdint.h>

#define Bq 2
#define Sq 2048
#define Dq 512
#define Hq 8

#define SDc  ((long)Sq * Dq)
#define SSc  ((long)Sq * Sq)
#define DDc  ((long)Dq * Dq)

#define X_PLANE    ((long)Bq * Sq * Dq)
#define W_PLANE    ((long)Hq * Dq * Dq)
#define QK_PLANE   ((long)Bq * Hq * Sq * Dq)
#define ATTN_PLANE ((long)Bq * Hq * Sq * Sq)
#define Z_PLANE    QK_PLANE

__device__ __align__(256) float g_attn[ATTN_PLANE];
__device__ __align__(256) __nv_bfloat16 g_xq [2 * X_PLANE];
__device__ __align__(256) __nv_bfloat16 g_xk [2 * X_PLANE];
__device__ __align__(256) __nv_bfloat16 g_xv [2 * X_PLANE];
__device__ __align__(256) __nv_bfloat16 g_wqt[2 * W_PLANE];
__device__ __align__(256) __nv_bfloat16 g_wkt[2 * W_PLANE];
__device__ __align__(256) __nv_bfloat16 g_wvt[2 * W_PLANE];
__device__ __align__(256) __nv_bfloat16 g_wzt[2 * W_PLANE];
__device__ __align__(256) __nv_bfloat16 g_qs [2 * QK_PLANE];
__device__ __align__(256) __nv_bfloat16 g_ks [2 * QK_PLANE];
__device__ __align__(256) __nv_bfloat16 g_vts[2 * QK_PLANE];   // [b,h,e,s]
__device__ __align__(256) __nv_bfloat16 g_zs [2 * Z_PLANE];    // [b,s,h*D]
__device__ __align__(256) __nv_bfloat16 g_ps [2 * ATTN_PLANE]; // split probs

struct Off { int dv; long s1; int md; long s2; };

__device__ __forceinline__ uint32_t smem_u32(const void* p) {
    uint32_t a;
    asm("{ .reg .u64 t; cvta.to.shared.u64 t, %1; cvt.u32.u64 %0, t; }" : "=r"(a) : "l"(p));
    return a;
}
__device__ __forceinline__ void cpasync16(uint32_t dst, const void* src) {
    asm volatile("cp.async.cg.shared.global [%0], [%1], 16;" :: "r"(dst), "l"(src) : "memory");
}
#define CP_COMMIT() asm volatile("cp.async.commit_group;" ::: "memory")
#define CP_WAIT1()  asm volatile("cp.async.wait_group 1;" ::: "memory")
#define CP_WAIT0()  asm volatile("cp.async.wait_group 0;" ::: "memory")

#define LDSM4(r, a) \
    asm volatile("ldmatrix.sync.aligned.m8n8.x4.shared.b16 {%0,%1,%2,%3}, [%4];" \
        : "=r"((r)[0]), "=r"((r)[1]), "=r"((r)[2]), "=r"((r)[3]) : "r"(a))

#define MMA(c, a, b0, b1) \
    asm volatile("mma.sync.aligned.m16n8k16.row.col.f32.bf16.bf16.f32 " \
        "{%0,%1,%2,%3},{%4,%5,%6,%7},{%8,%9},{%0,%1,%2,%3};" \
        : "+f"((c)[0]), "+f"((c)[1]), "+f"((c)[2]), "+f"((c)[3]) \
        : "r"((a)[0]), "r"((a)[1]), "r"((a)[2]), "r"((a)[3]), "r"(b0), "r"(b1))

__device__ __forceinline__ void split1(float x, __nv_bfloat16& h, __nv_bfloat16& l) {
    h = __float2bfloat16_rn(x);
    l = __float2bfloat16_rn(x - __bfloat162float(h));
}

#define STAGE_B  16384
#define STAGE_SZ 32768
#define NSTAGE   3
#define SMEM_SZ  (NSTAGE * STAGE_SZ)

// ---------------------------------------------------------------------------
// HMMA TN GEMM, 3-pass bf16 split, pass-major MMA order, 3-stage cp.async,
// 2 CTAs/SM. Block 128x128, K-chunk 32, 8 warps.
// Smem row: 128B = [32 bf16 hi | 32 bf16 lo], chunk XOR swizzle.
// mode 0: fp32 out (+bias). mode 1: split-bf16 out. mode 2: split-bf16 transposed.
// ---------------------------------------------------------------------------
__global__ void __launch_bounds__(256, 2)
gemm_mma(const __nv_bfloat16* __restrict__ A, long aplane,
         const __nv_bfloat16* __restrict__ B, long bplane,
         void* Cv, long cplane,
         int K, int lda, int ldb, int ldc,
         Off oa, Off ob, Off oc,
         float alpha, const float* __restrict__ bias, int mode)
{
    extern __shared__ char smem[];
    const uint32_t sm = smem_u32(smem);
    const int tid = threadIdx.x, wid = tid >> 5, lane = tid & 31;
    const int z = blockIdx.z;

    const __nv_bfloat16* Ahp = A + (long)(z / oa.dv) * oa.s1 + (long)(z % oa.md) * oa.s2;
    const __nv_bfloat16* Bhp = B + (long)(z / ob.dv) * ob.s1 + (long)(z % ob.md) * ob.s2;
    const long coff = (long)(z / oc.dv) * oc.s1 + (long)(z % oc.md) * oc.s2;

    const long row0 = (long)blockIdx.y * 128;
    const long col0 = (long)blockIdx.x * 128;

    // ---- loader mapping: 2 threads per row (hi / lo plane, 64B each)
    const int lrow = tid >> 1;
    const int lpl  = tid & 1;
    const __nv_bfloat16* Asrc = (lpl ? Ahp + aplane : Ahp) + (row0 + lrow) * lda;
    const __nv_bfloat16* Bsrc = (lpl ? Bhp + bplane : Bhp) + (col0 + lrow) * ldb;
    uint32_t soff[4];
    #pragma unroll
    for (int j = 0; j < 4; ++j) {
        const int c = lpl * 4 + j;
        soff[j] = lrow * 128 + ((c ^ (lrow & 7)) << 4);
    }

    // ---- compute mapping
    const int wm = wid & 1, wn = wid >> 1;
    const int g = lane >> 3, r8 = lane & 7;
    const int a_roff = ((g & 1) << 3) + r8;
    const int a_kh   = g >> 1;
    const int b_roff = ((g >> 1) << 3) + r8;
    const int b_kh   = g & 1;

    uint32_t a_row[4], a_rx[4];
    #pragma unroll
    for (int mt = 0; mt < 4; ++mt) {
        const int row = wm * 64 + mt * 16 + a_roff;
        a_row[mt] = row * 128;
        a_rx[mt] = row & 7;
    }
    uint32_t b_row[2], b_rx[2];
    #pragma unroll
    for (int np = 0; np < 2; ++np) {
        const int row = wn * 32 + np * 16 + b_roff;
        b_row[np] = row * 128;
        b_rx[np] = row & 7;
    }

    float acc[4][4][4];
    #pragma unroll
    for (int i = 0; i < 4; ++i)
        #pragma unroll
        for (int j = 0; j < 4; ++j)
            #pragma unroll
            for (int q = 0; q < 4; ++q) acc[i][j][q] = 0.0f;

    const int nst = K / 32;

    // prologue: stages 0, 1
    #pragma unroll
    for (int p = 0; p < 2; ++p) {
        if (p < nst) {
            const uint32_t tb = sm + p * STAGE_SZ;
            const long k0 = (long)p * 32;
            #pragma unroll
            for (int j = 0; j < 4; ++j) {
                cpasync16(tb + soff[j], Asrc + k0 + j * 8);
                cpasync16(tb + STAGE_B + soff[j], Bsrc + k0 + j * 8);
            }
        }
        CP_COMMIT();
    }

    int stg = 0;
    for (int s = 0; s < nst; ++s) {
        if (s + 1 < nst) CP_WAIT1(); else CP_WAIT0();
        __syncthreads();

        const uint32_t tb = sm + stg * STAGE_SZ;
        const uint32_t tba = tb, tbb = tb + STAGE_B;

        #pragma unroll
        for (int ks = 0; ks < 2; ++ks) {
            const int ca = ks * 2 + a_kh;
            const int cb = ks * 2 + b_kh;

            // ---- pass 1: Ah x Bh
            uint32_t Ahr[4][4], Bhr[2][4];
            #pragma unroll
            for (int mt = 0; mt < 4; ++mt)
                LDSM4(Ahr[mt], tba + a_row[mt] + ((ca ^ a_rx[mt]) << 4));
            #pragma unroll
            for (int np = 0; np < 2; ++np)
                LDSM4(Bhr[np], tbb + b_row[np] + ((cb ^ b_rx[np]) << 4));
            #pragma unroll
            for (int mt = 0; mt < 4; ++mt)
                #pragma unroll
                for (int nt = 0; nt < 4; ++nt) {
                    const int np = nt >> 1, s2 = (nt & 1) * 2;
                    MMA(acc[mt][nt], Ahr[mt], Bhr[np][s2], Bhr[np][s2 + 1]);
                }

            // ---- pass 2: Ah x Bl
            uint32_t Blr[2][4];
            #pragma unroll
            for (int np = 0; np < 2; ++np)
                LDSM4(Blr[np], tbb + b_row[np] + (((cb + 4) ^ b_rx[np]) << 4));
            #pragma unroll
            for (int mt = 0; mt < 4; ++mt)
                #pragma unroll
                for (int nt = 0; nt < 4; ++nt) {
                    const int np = nt >> 1, s2 = (nt & 1) * 2;
                    MMA(acc[mt][nt], Ahr[mt], Blr[np][s2], Blr[np][s2 + 1]);
                }

            // ---- pass 3: Al x Bh
            uint32_t Alr[4][4];
            #pragma unroll
            for (int mt = 0; mt < 4; ++mt)
                LDSM4(Alr[mt], tba + a_row[mt] + (((ca + 4) ^ a_rx[mt]) << 4));
            #pragma unroll
            for (int mt = 0; mt < 4; ++mt)
                #pragma unroll
                for (int nt = 0; nt < 4; ++nt) {
                    const int np = nt >> 1, s2 = (nt & 1) * 2;
                    MMA(acc[mt][nt], Alr[mt], Bhr[np][s2], Bhr[np][s2 + 1]);
                }
        }

        // prefetch stage s+2
        if (s + 2 < nst) {
            int ps = stg + 2; if (ps >= NSTAGE) ps -= NSTAGE;
            const uint32_t pb = sm + ps * STAGE_SZ;
            const long k0 = (long)(s + 2) * 32;
            #pragma unroll
            for (int j = 0; j < 4; ++j) {
                cpasync16(pb + soff[j], Asrc + k0 + j * 8);
                cpasync16(pb + STAGE_B + soff[j], Bsrc + k0 + j * 8);
            }
        }
        CP_COMMIT();

        if (++stg == NSTAGE) stg = 0;
    }

    // ---- epilogue
    const int r_in = lane >> 2, c_in = (lane & 3) * 2;
    #pragma unroll
    for (int mt = 0; mt < 4; ++mt) {
        #pragma unroll
        for (int half = 0; half < 2; ++half) {
            const long row = row0 + wm * 64 + mt * 16 + half * 8 + r_in;
            #pragma unroll
            for (int nt = 0; nt < 4; ++nt) {
                const int colg = (int)col0 + wn * 32 + nt * 8 + c_in;
                float v0 = acc[mt][nt][half * 2 + 0] * alpha;
                float v1 = acc[mt][nt][half * 2 + 1] * alpha;
                if (mode == 0) {
                    if (bias) { v0 += bias[colg]; v1 += bias[colg + 1]; }
                    *(float2*)((float*)Cv + coff + row * ldc + colg) = make_float2(v0, v1);
                } else if (mode == 1) {
                    __nv_bfloat16 h0, l0, h1, l1;
                    split1(v0, h0, l0); split1(v1, h1, l1);
                    __nv_bfloat162 hh; hh.x = h0; hh.y = h1;
                    __nv_bfloat162 ll; ll.x = l0; ll.y = l1;
                    __nv_bfloat16* Ch = (__nv_bfloat16*)Cv + coff + row * ldc + colg;
                    *(__nv_bfloat162*)Ch = hh;
                    *(__nv_bfloat162*)(Ch + cplane) = ll;
                } else {
                    __nv_bfloat16 h0, l0, h1, l1;
                    split1(v0, h0, l0); split1(v1, h1, l1);
                    __nv_bfloat16* Ch = (__nv_bfloat16*)Cv + coff;
                    const long o0 = (long)colg * ldc + row;
                    const long o1 = (long)(colg + 1) * ldc + row;
                    Ch[o0] = h0; Ch[o0 + cplane] = l0;
                    Ch[o1] = h1; Ch[o1 + cplane] = l1;
                }
            }
        }
    }
}

// ---------------------------------------------------------------------------
__global__ void __launch_bounds__(256) split_kernel(const float* __restrict__ in,
                                                    __nv_bfloat16* __restrict__ hi, long plane)
{
    const long idx = (long)blockIdx.x * 256 + threadIdx.x;
    float4 v = ((const float4*)in)[idx];
    __nv_bfloat16 h0, l0, h1, l1, h2, l2, h3, l3;
    split1(v.x, h0, l0); split1(v.y, h1, l1);
    split1(v.z, h2, l2); split1(v.w, h3, l3);
    __nv_bfloat162 a, b, c, d;
    a.x = h0; a.y = h1; b.x = h2; b.y = h3;
    c.x = l0; c.y = l1; d.x = l2; d.y = l3;
    ((__nv_bfloat162*)hi)[2 * idx]     = a;
    ((__nv_bfloat162*)hi)[2 * idx + 1] = b;
    ((__nv_bfloat162*)(hi + plane))[2 * idx]     = c;
    ((__nv_bfloat162*)(hi + plane))[2 * idx + 1] = d;
}

// transpose + split: in [z][R][C] fp32 -> out [z][C][R] bf16 hi/lo
__global__ void __launch_bounds__(256) tsplit_kernel(const float* __restrict__ in,
                                                     __nv_bfloat16* __restrict__ outh,
                                                     long plane, int R, int C)
{
    __shared__ float ts[32][33];
    const int tx = threadIdx.x, ty = threadIdx.y;
    const long zo = (long)blockIdx.z * R * C;
    const int r0 = blockIdx.y * 32, c0 = blockIdx.x * 32;
    #pragma unroll
    for (int i = 0; i < 4; ++i)
        ts[ty + 8 * i][tx] = in[zo + (long)(r0 + ty + 8 * i) * C + c0 + tx];
    __syncthreads();
    #pragma unroll
    for (int i = 0; i < 4; ++i) {
        __nv_bfloat16 h, l;
        split1(ts[tx][ty + 8 * i], h, l);
        const long o = zo + (long)(c0 + ty + 8 * i) * R + r0 + tx;
        outh[o] = h;
        outh[o + plane] = l;
    }
}

// softmax over fp32 rows of g_attn -> split bf16 probs in g_ps
__global__ void __launch_bounds__(256) softmax_kernel()
{
    const long rowo = (long)blockIdx.x * Sq;
    const float* p = g_attn + rowo;
    const int tid = threadIdx.x;

    float v[8];
    float mx = -1e30f;
    #pragma unroll
    for (int i = 0; i < 8; ++i) { v[i] = p[tid + i * 256]; mx = fmaxf(mx, v[i]); }
    #pragma unroll
    for (int o = 16; o > 0; o >>= 1) mx = fmaxf(mx, __shfl_xor_sync(~0u, mx, o));
    __shared__ float sr[8];
    if ((tid & 31) == 0) sr[tid >> 5] = mx;
    __syncthreads();
    float m = sr[0];
    #pragma unroll
    for (int i = 1; i < 8; ++i) m = fmaxf(m, sr[i]);
    __syncthreads();
    float s = 0.f;
    #pragma unroll
    for (int i = 0; i < 8; ++i) { v[i] = __expf(v[i] - m); s += v[i]; }
    #pragma unroll
    for (int o = 16; o > 0; o >>= 1) s += __shfl_xor_sync(~0u, s, o);
    if ((tid & 31) == 0) sr[tid >> 5] = s;
    __syncthreads();
    float t = 0.f;
    #pragma unroll
    for (int i = 0; i < 8; ++i) t += sr[i];
    const float inv = 1.0f / t;
    #pragma unroll
    for (int i = 0; i < 8; ++i) {
        __nv_bfloat16 h, l;
        split1(v[i] * inv, h, l);
        g_ps[rowo + tid + i * 256] = h;
        g_ps[ATTN_PLANE + rowo + tid + i * 256] = l;
    }
}

// attn_avg from split probs
__global__ void __launch_bounds__(256) avg_kernel(float* __restrict__ out)
{
    const long p2 = (long)blockIdx.x * 256 + threadIdx.x;
    const long per_b = SSc / 2;
    const long b = p2 / per_b, r = p2 % per_b;
    const __nv_bfloat162* hi = (const __nv_bfloat162*)g_ps;
    const __nv_bfloat162* lo = (const __nv_bfloat162*)(g_ps + ATTN_PLANE);
    float2 acc = make_float2(0.f, 0.f);
    #pragma unroll
    for (int h = 0; h < Hq; ++h) {
        const long o = (b * Hq + h) * per_b + r;
        __nv_bfloat162 a = hi[o], c = lo[o];
        acc.x += __bfloat162float(a.x) + __bfloat162float(c.x);
        acc.y += __bfloat162float(a.y) + __bfloat162float(c.y);
    }
    acc.x *= 0.125f; acc.y *= 0.125f;
    ((float2*)out)[p2] = acc;
}

// ---------------------------------------------------------------------------
extern "C" void kernel_launch(void* const* d_in, const int* in_sizes, int n_in,
                              void* d_out, int out_size)
{
    (void)in_sizes; (void)n_in; (void)out_size;
    const float* Xq = (const float*)d_in[0];
    const float* Xk = (const float*)d_in[1];
    const float* Xv = (const float*)d_in[2];
    const float* Wq = (const float*)d_in[3];
    const float* Wk = (const float*)d_in[4];
    const float* Wv = (const float*)d_in[5];
    const float* Wz = (const float*)d_in[6];
    const float* bz = (const float*)d_in[7];
    float* out = (float*)d_out;
    float* attn_avg = out + (long)Bq * Sq * Dq;

    __nv_bfloat16 *pxq, *pxk, *pxv, *pwq, *pwk, *pwv, *pwz, *pqs, *pks, *pvt, *pzs, *pps;
    float* pattn;
    cudaGetSymbolAddress((void**)&pxq, g_xq);
    cudaGetSymbolAddress((void**)&pxk, g_xk);
    cudaGetSymbolAddress((void**)&pxv, g_xv);
    cudaGetSymbolAddress((void**)&pwq, g_wqt);
    cudaGetSymbolAddress((void**)&pwk, g_wkt);
    cudaGetSymbolAddress((void**)&pwv, g_wvt);
    cudaGetSymbolAddress((void**)&pwz, g_wzt);
    cudaGetSymbolAddress((void**)&pqs, g_qs);
    cudaGetSymbolAddress((void**)&pks, g_ks);
    cudaGetSymbolAddress((void**)&pvt, g_vts);
    cudaGetSymbolAddress((void**)&pzs, g_zs);
    cudaGetSymbolAddress((void**)&pps, g_ps);
    cudaGetSymbolAddress((void**)&pattn, g_attn);

    cudaFuncSetAttribute(gemm_mma, cudaFuncAttributeMaxDynamicSharedMemorySize, SMEM_SZ);

    const float inv4 = (float)(1.0 / pow((double)Dq, 0.25));

    // 1) split inputs; transpose+split weights
    {
        int nb = (int)(X_PLANE / 1024);
        split_kernel<<<nb, 256>>>(Xq, pxq, X_PLANE);
        split_kernel<<<nb, 256>>>(Xk, pxk, X_PLANE);
        split_kernel<<<nb, 256>>>(Xv, pxv, X_PLANE);
        dim3 tb(32, 8);
        tsplit_kernel<<<dim3(16, 16, 8), tb>>>(Wq, pwq, W_PLANE, Dq, Dq);
        tsplit_kernel<<<dim3(16, 16, 8), tb>>>(Wk, pwk, W_PLANE, Dq, Dq);
        tsplit_kernel<<<dim3(16, 16, 8), tb>>>(Wv, pwv, W_PLANE, Dq, Dq);
        tsplit_kernel<<<dim3(16, 128, 1), tb>>>(Wz, pwz, W_PLANE, Hq * Dq, Dq);
    }

    // 2) projections: [S,512] = X[b] @ Wt[h]^T (TN), z = b*H+h
    {
        dim3 grid(Dq / 128, Sq / 128, Bq * Hq);
        Off oa = { Hq, SDc, 1, 0 };
        Off ob = { 1, 0, Hq, DDc };
        Off oc = { 1, SDc, 1, 0 };
        gemm_mma<<<grid, 256, SMEM_SZ>>>(pxq, X_PLANE, pwq, W_PLANE, pqs, QK_PLANE,
                                         Dq, Dq, Dq, Dq, oa, ob, oc, inv4, nullptr, 1);
        gemm_mma<<<grid, 256, SMEM_SZ>>>(pxk, X_PLANE, pwk, W_PLANE, pks, QK_PLANE,
                                         Dq, Dq, Dq, Dq, oa, ob, oc, inv4, nullptr, 1);
        gemm_mma<<<grid, 256, SMEM_SZ>>>(pxv, X_PLANE, pwv, W_PLANE, pvt, QK_PLANE,
                                         Dq, Dq, Dq, Sq, oa, ob, oc, 1.0f, nullptr, 2);
    }

    // 3) scores (fp32) = Q @ K^T
    {
        dim3 grid(Sq / 128, Sq / 128, Bq * Hq);
        Off oa = { 1, SDc, 1, 0 };
        Off ob = { 1, SDc, 1, 0 };
        Off oc = { 1, SSc, 1, 0 };
        gemm_mma<<<grid, 256, SMEM_SZ>>>(pqs, QK_PLANE, pks, QK_PLANE, pattn, 0,
                                         Dq, Dq, Dq, Sq, oa, ob, oc, 1.0f, nullptr, 0);
    }

    // 4) softmax -> split probs; 5) head average
    softmax_kernel<<<Bq * Hq * Sq, 256>>>();
    avg_kernel<<<(int)(Bq * SSc / 2 / 256), 256>>>(attn_avg);

    // 6) z = P @ V (B = V^T, TN), concat-layout split output
    {
        dim3 grid(Dq / 128, Sq / 128, Bq * Hq);
        Off oa = { 1, SSc, 1, 0 };
        Off ob = { 1, SDc, 1, 0 };
        Off oc = { Hq, (long)Sq * Hq * Dq, Hq, (long)Dq };
        gemm_mma<<<grid, 256, SMEM_SZ>>>(pps, ATTN_PLANE, pvt, QK_PLANE, pzs, Z_PLANE,
                                         Sq, Sq, Sq, Hq * Dq, oa, ob, oc, 1.0f, nullptr, 1);
    }

    // 7) out = Z @ Wz^T + bz (fp32)
    {
        dim3 grid(Dq / 128, (Bq * Sq) / 128, 1);
        Off oz = { 1, 0, 1, 0 };
        gemm_mma<<<grid, 256, SMEM_SZ>>>(pzs, Z_PLANE, pwz, W_PLANE, out, 0,
                                         Hq * Dq, Hq * Dq, Hq * Dq, Dq,
                                         oz, oz, oz, 1.0f, bz, 0);
    }
}

// round 7
// speedup vs baseline: 2.8129x; 1.2972x over previous
#include <cuda_runtime.h>
#include <cuda_fp16.h>
#include <math.h>
#include <stdint.h>

#define Bq 2
#define Sq 2048
#define Dq 512
#define Hq 8

#define SDc  ((long)Sq * Dq)
#define SSc  ((long)Sq * Sq)
#define DDc  ((long)Dq * Dq)

#define X_PLANE    ((long)Bq * Sq * Dq)
#define W_PLANE    ((long)Hq * Dq * Dq)
#define QK_PLANE   ((long)Bq * Hq * Sq * Dq)
#define ATTN_PLANE ((long)Bq * Hq * Sq * Sq)
#define Z_PLANE    QK_PLANE

__device__ __align__(256) float g_attn[ATTN_PLANE];
__device__ __align__(256) __half g_xq [2 * X_PLANE];
__device__ __align__(256) __half g_xk [2 * X_PLANE];
__device__ __align__(256) __half g_xv [2 * X_PLANE];
__device__ __align__(256) __half g_wqt[2 * W_PLANE];
__device__ __align__(256) __half g_wkt[2 * W_PLANE];
__device__ __align__(256) __half g_wvt[2 * W_PLANE];
__device__ __align__(256) __half g_wzt[2 * W_PLANE];
__device__ __align__(256) __half g_qs [2 * QK_PLANE];
__device__ __align__(256) __half g_ks [2 * QK_PLANE];
__device__ __align__(256) __half g_vts[2 * QK_PLANE];   // [b,h,e,s]
__device__ __align__(256) __half g_zs [2 * Z_PLANE];    // [b,s,h*D]
__device__ __align__(256) __half g_ps [2 * ATTN_PLANE]; // split probs (x1024)

struct Off { int dv; long s1; int md; long s2; };

__device__ __forceinline__ uint32_t smem_u32(const void* p) {
    uint32_t a;
    asm("{ .reg .u64 t; cvta.to.shared.u64 t, %1; cvt.u32.u64 %0, t; }" : "=r"(a) : "l"(p));
    return a;
}
__device__ __forceinline__ void cpasync16(uint32_t dst, const void* src) {
    asm volatile("cp.async.cg.shared.global [%0], [%1], 16;" :: "r"(dst), "l"(src) : "memory");
}
#define CP_COMMIT() asm volatile("cp.async.commit_group;" ::: "memory")
#define CP_WAIT1()  asm volatile("cp.async.wait_group 1;" ::: "memory")
#define CP_WAIT0()  asm volatile("cp.async.wait_group 0;" ::: "memory")

#define LDSM4(r, a) \
    asm volatile("ldmatrix.sync.aligned.m8n8.x4.shared.b16 {%0,%1,%2,%3}, [%4];" \
        : "=r"((r)[0]), "=r"((r)[1]), "=r"((r)[2]), "=r"((r)[3]) : "r"(a))

// f32-accumulate HMMA (full precision main pass)
#define MMAF(c, a, b0, b1) \
    asm volatile("mma.sync.aligned.m16n8k16.row.col.f32.f16.f16.f32 " \
        "{%0,%1,%2,%3},{%4,%5,%6,%7},{%8,%9},{%0,%1,%2,%3};" \
        : "+f"((c)[0]), "+f"((c)[1]), "+f"((c)[2]), "+f"((c)[3]) \
        : "r"((a)[0]), "r"((a)[1]), "r"((a)[2]), "r"((a)[3]), "r"(b0), "r"(b1))

// f16-accumulate HMMA (correction passes; 2x rate expected)
#define MMAH(c, a, b0, b1) \
    asm volatile("mma.sync.aligned.m16n8k16.row.col.f16.f16.f16.f16 " \
        "{%0,%1},{%2,%3,%4,%5},{%6,%7},{%0,%1};" \
        : "+r"((c)[0]), "+r"((c)[1]) \
        : "r"((a)[0]), "r"((a)[1]), "r"((a)[2]), "r"((a)[3]), "r"(b0), "r"(b1))

__device__ __forceinline__ void split1(float x, __half& h, __half& l) {
    h = __float2half_rn(x);
    l = __float2half_rn(x - __half2float(h));
}

#define STAGE_B  16384
#define STAGE_SZ 32768
#define NSTAGE   3
#define SMEM_SZ  (NSTAGE * STAGE_SZ)
#define GTHREADS 512

// ---------------------------------------------------------------------------
// HMMA TN GEMM, fp16 3-pass split (hh:f32acc, hl+lh:f16acc), 3-stage cp.async.
// Block 128x128, K-chunk 32, 16 warps (warp tile 32x32), 512 threads.
// Smem row: 128B = [32 fp16 hi | 32 fp16 lo], chunk XOR swizzle.
// mode 0: fp32 out (+bias). mode 1: split-fp16 out. mode 2: split-fp16 transposed.
// ---------------------------------------------------------------------------
__global__ void __launch_bounds__(GTHREADS, 1)
gemm_mma(const __half* __restrict__ A, long aplane,
         const __half* __restrict__ B, long bplane,
         void* Cv, long cplane,
         int K, int lda, int ldb, int ldc,
         Off oa, Off ob, Off oc,
         float alpha, const float* __restrict__ bias, int mode)
{
    extern __shared__ char smem[];
    const uint32_t sm = smem_u32(smem);
    const int tid = threadIdx.x, wid = tid >> 5, lane = tid & 31;
    const int z = blockIdx.z;

    const __half* Ahp = A + (long)(z / oa.dv) * oa.s1 + (long)(z % oa.md) * oa.s2;
    const __half* Bhp = B + (long)(z / ob.dv) * ob.s1 + (long)(z % ob.md) * ob.s2;
    const long coff = (long)(z / oc.dv) * oc.s1 + (long)(z % oc.md) * oc.s2;

    const long row0 = (long)blockIdx.y * 128;
    const long col0 = (long)blockIdx.x * 128;

    // ---- loader mapping: 4 threads per row; each thread 2 chunks (16B) per matrix
    const int lrow = tid >> 2;              // 0..127
    const int c0   = (tid & 3) * 2;         // chunk pair base: 0,2,4,6
    const int lpl  = c0 >> 2;               // 0 = hi plane, 1 = lo plane
    const __half* Asrc = (lpl ? Ahp + aplane : Ahp) + (row0 + lrow) * lda + (c0 & 3) * 8;
    const __half* Bsrc = (lpl ? Bhp + bplane : Bhp) + (col0 + lrow) * ldb + (c0 & 3) * 8;
    uint32_t soff[2];
    #pragma unroll
    for (int j = 0; j < 2; ++j)
        soff[j] = lrow * 128 + (((c0 + j) ^ (lrow & 7)) << 4);

    // ---- compute mapping: warp grid 4(m) x 4(n), warp tile 32x32
    const int wm = wid & 3, wn = wid >> 2;
    const int g = lane >> 3, r8 = lane & 7;
    const int a_roff = ((g & 1) << 3) + r8;
    const int a_kh   = g >> 1;
    const int b_roff = ((g >> 1) << 3) + r8;
    const int b_kh   = g & 1;

    uint32_t a_row[2], a_rx[2];
    #pragma unroll
    for (int mt = 0; mt < 2; ++mt) {
        const int row = wm * 32 + mt * 16 + a_roff;
        a_row[mt] = row * 128;
        a_rx[mt] = row & 7;
    }
    uint32_t b_row[2], b_rx[2];
    #pragma unroll
    for (int np = 0; np < 2; ++np) {
        const int row = wn * 32 + np * 16 + b_roff;
        b_row[np] = row * 128;
        b_rx[np] = row & 7;
    }

    float acc[2][4][4];
    uint32_t acch[2][4][2];
    #pragma unroll
    for (int i = 0; i < 2; ++i)
        #pragma unroll
        for (int j = 0; j < 4; ++j) {
            #pragma unroll
            for (int q = 0; q < 4; ++q) acc[i][j][q] = 0.0f;
            acch[i][j][0] = 0u; acch[i][j][1] = 0u;
        }

    const int nst = K / 32;

    // prologue: stages 0, 1
    #pragma unroll
    for (int p = 0; p < 2; ++p) {
        if (p < nst) {
            const uint32_t tb = sm + p * STAGE_SZ;
            const long k0 = (long)p * 32;
            #pragma unroll
            for (int j = 0; j < 2; ++j) {
                cpasync16(tb + soff[j], Asrc + k0 + j * 8);
                cpasync16(tb + STAGE_B + soff[j], Bsrc + k0 + j * 8);
            }
        }
        CP_COMMIT();
    }

    int stg = 0;
    for (int s = 0; s < nst; ++s) {
        if (s + 1 < nst) CP_WAIT1(); else CP_WAIT0();
        __syncthreads();

        const uint32_t tb = sm + stg * STAGE_SZ;
        const uint32_t tba = tb, tbb = tb + STAGE_B;

        #pragma unroll
        for (int ks = 0; ks < 2; ++ks) {
            const int ca = ks * 2 + a_kh;
            const int cb = ks * 2 + b_kh;

            // ---- pass 1: Ah x Bh (f32 acc)
            uint32_t Ahr[2][4], Bhr[2][4];
            #pragma unroll
            for (int mt = 0; mt < 2; ++mt)
                LDSM4(Ahr[mt], tba + a_row[mt] + ((ca ^ a_rx[mt]) << 4));
            #pragma unroll
            for (int np = 0; np < 2; ++np)
                LDSM4(Bhr[np], tbb + b_row[np] + ((cb ^ b_rx[np]) << 4));
            #pragma unroll
            for (int mt = 0; mt < 2; ++mt)
                #pragma unroll
                for (int nt = 0; nt < 4; ++nt) {
                    const int np = nt >> 1, s2 = (nt & 1) * 2;
                    MMAF(acc[mt][nt], Ahr[mt], Bhr[np][s2], Bhr[np][s2 + 1]);
                }

            // ---- pass 2: Ah x Bl (f16 acc)
            uint32_t Blr[2][4];
            #pragma unroll
            for (int np = 0; np < 2; ++np)
                LDSM4(Blr[np], tbb + b_row[np] + (((cb + 4) ^ b_rx[np]) << 4));
            #pragma unroll
            for (int mt = 0; mt < 2; ++mt)
                #pragma unroll
                for (int nt = 0; nt < 4; ++nt) {
                    const int np = nt >> 1, s2 = (nt & 1) * 2;
                    MMAH(acch[mt][nt], Ahr[mt], Blr[np][s2], Blr[np][s2 + 1]);
                }

            // ---- pass 3: Al x Bh (f16 acc)
            uint32_t Alr[2][4];
            #pragma unroll
            for (int mt = 0; mt < 2; ++mt)
                LDSM4(Alr[mt], tba + a_row[mt] + (((ca + 4) ^ a_rx[mt]) << 4));
            #pragma unroll
            for (int mt = 0; mt < 2; ++mt)
                #pragma unroll
                for (int nt = 0; nt < 4; ++nt) {
                    const int np = nt >> 1, s2 = (nt & 1) * 2;
                    MMAH(acch[mt][nt], Alr[mt], Bhr[np][s2], Bhr[np][s2 + 1]);
                }
        }

        // prefetch stage s+2
        if (s + 2 < nst) {
            int ps = stg + 2; if (ps >= NSTAGE) ps -= NSTAGE;
            const uint32_t pb = sm + ps * STAGE_SZ;
            const long k0 = (long)(s + 2) * 32;
            #pragma unroll
            for (int j = 0; j < 2; ++j) {
                cpasync16(pb + soff[j], Asrc + k0 + j * 8);
                cpasync16(pb + STAGE_B + soff[j], Bsrc + k0 + j * 8);
            }
        }
        CP_COMMIT();

        if (++stg == NSTAGE) stg = 0;
    }

    // ---- epilogue: fold f16 corrections, scale, store
    const int r_in = lane >> 2, c_in = (lane & 3) * 2;
    #pragma unroll
    for (int mt = 0; mt < 2; ++mt) {
        #pragma unroll
        for (int half = 0; half < 2; ++half) {
            const long row = row0 + wm * 32 + mt * 16 + half * 8 + r_in;
            #pragma unroll
            for (int nt = 0; nt < 4; ++nt) {
                const int colg = (int)col0 + wn * 32 + nt * 8 + c_in;
                float2 cf = __half22float2(*reinterpret_cast<__half2*>(&acch[mt][nt][half]));
                float v0 = (acc[mt][nt][half * 2 + 0] + cf.x) * alpha;
                float v1 = (acc[mt][nt][half * 2 + 1] + cf.y) * alpha;
                if (mode == 0) {
                    if (bias) { v0 += bias[colg]; v1 += bias[colg + 1]; }
                    *(float2*)((float*)Cv + coff + row * ldc + colg) = make_float2(v0, v1);
                } else if (mode == 1) {
                    __half h0, l0, h1, l1;
                    split1(v0, h0, l0); split1(v1, h1, l1);
                    __half2 hh; hh.x = h0; hh.y = h1;
                    __half2 ll; ll.x = l0; ll.y = l1;
                    __half* Ch = (__half*)Cv + coff + row * ldc + colg;
                    *(__half2*)Ch = hh;
                    *(__half2*)(Ch + cplane) = ll;
                } else {
                    __half h0, l0, h1, l1;
                    split1(v0, h0, l0); split1(v1, h1, l1);
                    __half* Ch = (__half*)Cv + coff;
                    const long o0 = (long)colg * ldc + row;
                    const long o1 = (long)(colg + 1) * ldc + row;
                    Ch[o0] = h0; Ch[o0 + cplane] = l0;
                    Ch[o1] = h1; Ch[o1 + cplane] = l1;
                }
            }
        }
    }
}

// ---------------------------------------------------------------------------
__global__ void __launch_bounds__(256) split_kernel(const float* __restrict__ in,
                                                    __half* __restrict__ hi, long plane,
                                                    float scale)
{
    const long idx = (long)blockIdx.x * 256 + threadIdx.x;
    float4 v = ((const float4*)in)[idx];
    __half h0, l0, h1, l1, h2, l2, h3, l3;
    split1(v.x * scale, h0, l0); split1(v.y * scale, h1, l1);
    split1(v.z * scale, h2, l2); split1(v.w * scale, h3, l3);
    __half2 a, b, c, d;
    a.x = h0; a.y = h1; b.x = h2; b.y = h3;
    c.x = l0; c.y = l1; d.x = l2; d.y = l3;
    ((__half2*)hi)[2 * idx]     = a;
    ((__half2*)hi)[2 * idx + 1] = b;
    ((__half2*)(hi + plane))[2 * idx]     = c;
    ((__half2*)(hi + plane))[2 * idx + 1] = d;
}

// transpose + split: in [z][R][C] fp32 -> out [z][C][R] fp16 hi/lo (scaled)
__global__ void __launch_bounds__(256) tsplit_kernel(const float* __restrict__ in,
                                                     __half* __restrict__ outh,
                                                     long plane, int R, int C, float scale)
{
    __shared__ float ts[32][33];
    const int tx = threadIdx.x, ty = threadIdx.y;
    const long zo = (long)blockIdx.z * R * C;
    const int r0 = blockIdx.y * 32, c0 = blockIdx.x * 32;
    #pragma unroll
    for (int i = 0; i < 4; ++i)
        ts[ty + 8 * i][tx] = in[zo + (long)(r0 + ty + 8 * i) * C + c0 + tx];
    __syncthreads();
    #pragma unroll
    for (int i = 0; i < 4; ++i) {
        __half h, l;
        split1(ts[tx][ty + 8 * i] * scale, h, l);
        const long o = zo + (long)(c0 + ty + 8 * i) * R + r0 + tx;
        outh[o] = h;
        outh[o + plane] = l;
    }
}

// softmax over fp32 rows of g_attn -> split fp16 probs (x1024) in g_ps
__global__ void __launch_bounds__(256) softmax_kernel()
{
    const long rowo = (long)blockIdx.x * Sq;
    const float* p = g_attn + rowo;
    const int tid = threadIdx.x;

    float v[8];
    float mx = -1e30f;
    #pragma unroll
    for (int i = 0; i < 8; ++i) { v[i] = p[tid + i * 256]; mx = fmaxf(mx, v[i]); }
    #pragma unroll
    for (int o = 16; o > 0; o >>= 1) mx = fmaxf(mx, __shfl_xor_sync(~0u, mx, o));
    __shared__ float sr[8];
    if ((tid & 31) == 0) sr[tid >> 5] = mx;
    __syncthreads();
    float m = sr[0];
    #pragma unroll
    for (int i = 1; i < 8; ++i) m = fmaxf(m, sr[i]);
    __syncthreads();
    float s = 0.f;
    #pragma unroll
    for (int i = 0; i < 8; ++i) { v[i] = __expf(v[i] - m); s += v[i]; }
    #pragma unroll
    for (int o = 16; o > 0; o >>= 1) s += __shfl_xor_sync(~0u, s, o);
    if ((tid & 31) == 0) sr[tid >> 5] = s;
    __syncthreads();
    float t = 0.f;
    #pragma unroll
    for (int i = 0; i < 8; ++i) t += sr[i];
    const float inv = 1024.0f / t;   // scale probs by 1024
    #pragma unroll
    for (int i = 0; i < 8; ++i) {
        __half h, l;
        split1(v[i] * inv, h, l);
        g_ps[rowo + tid + i * 256] = h;
        g_ps[ATTN_PLANE + rowo + tid + i * 256] = l;
    }
}

// attn_avg from split probs (undo x1024 and /8 heads)
__global__ void __launch_bounds__(256) avg_kernel(float* __restrict__ out)
{
    const long p2 = (long)blockIdx.x * 256 + threadIdx.x;
    const long per_b = SSc / 2;
    const long b = p2 / per_b, r = p2 % per_b;
    const __half2* hi = (const __half2*)g_ps;
    const __half2* lo = (const __half2*)(g_ps + ATTN_PLANE);
    float2 acc = make_float2(0.f, 0.f);
    #pragma unroll
    for (int h = 0; h < Hq; ++h) {
        const long o = (b * Hq + h) * per_b + r;
        float2 a = __half22float2(hi[o]);
        float2 c = __half22float2(lo[o]);
        acc.x += a.x + c.x;
        acc.y += a.y + c.y;
    }
    const float f = 1.0f / 8192.0f;   // (1/8 heads) * (1/1024 scale)
    acc.x *= f; acc.y *= f;
    ((float2*)out)[p2] = acc;
}

// ---------------------------------------------------------------------------
extern "C" void kernel_launch(void* const* d_in, const int* in_sizes, int n_in,
                              void* d_out, int out_size)
{
    (void)in_sizes; (void)n_in; (void)out_size;
    const float* Xq = (const float*)d_in[0];
    const float* Xk = (const float*)d_in[1];
    const float* Xv = (const float*)d_in[2];
    const float* Wq = (const float*)d_in[3];
    const float* Wk = (const float*)d_in[4];
    const float* Wv = (const float*)d_in[5];
    const float* Wz = (const float*)d_in[6];
    const float* bz = (const float*)d_in[7];
    float* out = (float*)d_out;
    float* attn_avg = out + (long)Bq * Sq * Dq;

    __half *pxq, *pxk, *pxv, *pwq, *pwk, *pwv, *pwz, *pqs, *pks, *pvt, *pzs, *pps;
    float* pattn;
    cudaGetSymbolAddress((void**)&pxq, g_xq);
    cudaGetSymbolAddress((void**)&pxk, g_xk);
    cudaGetSymbolAddress((void**)&pxv, g_xv);
    cudaGetSymbolAddress((void**)&pwq, g_wqt);
    cudaGetSymbolAddress((void**)&pwk, g_wkt);
    cudaGetSymbolAddress((void**)&pwv, g_wvt);
    cudaGetSymbolAddress((void**)&pwz, g_wzt);
    cudaGetSymbolAddress((void**)&pqs, g_qs);
    cudaGetSymbolAddress((void**)&pks, g_ks);
    cudaGetSymbolAddress((void**)&pvt, g_vts);
    cudaGetSymbolAddress((void**)&pzs, g_zs);
    cudaGetSymbolAddress((void**)&pps, g_ps);
    cudaGetSymbolAddress((void**)&pattn, g_attn);

    cudaFuncSetAttribute(gemm_mma, cudaFuncAttributeMaxDynamicSharedMemorySize, SMEM_SZ);

    const float inv4 = (float)(1.0 / pow((double)Dq, 0.25));

    // 1) split inputs (scale 1); transpose+split weights (Wq/k/v x16, Wz x64)
    {
        int nb = (int)(X_PLANE / 1024);
        split_kernel<<<nb, 256>>>(Xq, pxq, X_PLANE, 1.0f);
        split_kernel<<<nb, 256>>>(Xk, pxk, X_PLANE, 1.0f);
        split_kernel<<<nb, 256>>>(Xv, pxv, X_PLANE, 1.0f);
        dim3 tb(32, 8);
        tsplit_kernel<<<dim3(16, 16, 8), tb>>>(Wq, pwq, W_PLANE, Dq, Dq, 16.0f);
        tsplit_kernel<<<dim3(16, 16, 8), tb>>>(Wk, pwk, W_PLANE, Dq, Dq, 16.0f);
        tsplit_kernel<<<dim3(16, 16, 8), tb>>>(Wv, pwv, W_PLANE, Dq, Dq, 16.0f);
        tsplit_kernel<<<dim3(16, 128, 1), tb>>>(Wz, pwz, W_PLANE, Hq * Dq, Dq, 64.0f);
    }

    // 2) projections (TN). Stored q_s = 4*q_true, k_s = 4*k_true, v_s = 4*v.
    //    acc = 16*(X.W) => alpha_qk = inv4/4, alpha_v = 1/4.
    {
        dim3 grid(Dq / 128, Sq / 128, Bq * Hq);
        Off oa = { Hq, SDc, 1, 0 };
        Off ob = { 1, 0, Hq, DDc };
        Off oc = { 1, SDc, 1, 0 };
        gemm_mma<<<grid, GTHREADS, SMEM_SZ>>>(pxq, X_PLANE, pwq, W_PLANE, pqs, QK_PLANE,
                                              Dq, Dq, Dq, Dq, oa, ob, oc, inv4 * 0.25f, nullptr, 1);
        gemm_mma<<<grid, GTHREADS, SMEM_SZ>>>(pxk, X_PLANE, pwk, W_PLANE, pks, QK_PLANE,
                                              Dq, Dq, Dq, Dq, oa, ob, oc, inv4 * 0.25f, nullptr, 1);
        gemm_mma<<<grid, GTHREADS, SMEM_SZ>>>(pxv, X_PLANE, pwv, W_PLANE, pvt, QK_PLANE,
                                              Dq, Dq, Dq, Sq, oa, ob, oc, 0.25f, nullptr, 2);
    }

    // 3) scores (fp32) = q_s.k_s / 16
    {
        dim3 grid(Sq / 128, Sq / 128, Bq * Hq);
        Off oa = { 1, SDc, 1, 0 };
        Off ob = { 1, SDc, 1, 0 };
        Off oc = { 1, SSc, 1, 0 };
        gemm_mma<<<grid, GTHREADS, SMEM_SZ>>>(pqs, QK_PLANE, pks, QK_PLANE, pattn, 0,
                                              Dq, Dq, Dq, Sq, oa, ob, oc, 1.0f / 16.0f, nullptr, 0);
    }

    // 4) softmax -> split probs (x1024); 5) head average
    softmax_kernel<<<Bq * Hq * Sq, 256>>>();
    avg_kernel<<<(int)(Bq * SSc / 2 / 256), 256>>>(attn_avg);

    // 6) z_s = 32*z = (p_s . v_s) / 128, concat-layout split output
    {
        dim3 grid(Dq / 128, Sq / 128, Bq * Hq);
        Off oa = { 1, SSc, 1, 0 };
        Off ob = { 1, SDc, 1, 0 };
        Off oc = { Hq, (long)Sq * Hq * Dq, Hq, (long)Dq };
        gemm_mma<<<grid, GTHREADS, SMEM_SZ>>>(pps, ATTN_PLANE, pvt, QK_PLANE, pzs, Z_PLANE,
                                              Sq, Sq, Sq, Hq * Dq, oa, ob, oc, 1.0f / 128.0f, nullptr, 1);
    }

    // 7) out = (z_s . wz_s)/2048 + bz (fp32)
    {
        dim3 grid(Dq / 128, (Bq * Sq) / 128, 1);
        Off oz = { 1, 0, 1, 0 };
        gemm_mma<<<grid, GTHREADS, SMEM_SZ>>>(pzs, Z_PLANE, pwz, W_PLANE, out, 0,
                                              Hq * Dq, Hq * Dq, Hq * Dq, Dq,
                                              oz, oz, oz, 1.0f / 2048.0f, bz, 0);
    }
}